// round 7
// baseline (speedup 1.0000x reference)
#include <cuda_runtime.h>
#include <cuda_bf16.h>
#include <math.h>

// B=16, C=22, L=3000, D=64, D2=256, E=8, T=4, K=13
// Only output token n=0 matters -> only tokens n=0..6 (conv q=0..17, x[:, :, 0..40]).

__device__ float g_cwT[286 * 64];        // transposed conv_w: [(c*13+k)][d]
__device__ float g_hln[16 * 448];        // LN'd tokens [b][n=0..6][d]   (n=0 = cls)
__device__ float g_tp[16 * 256];         // tokens_pre [b][o]
__device__ float g_tok[16 * 256];        // post LN+GELU tokens [b][o]
__device__ float g_tokT[256 * 16];       // transposed tokens [d][b]
__device__ float g_coef[16 * 16];        // per-b coef for 9 matrices (0 if unselected)
__device__ float g_ye[9 * 16 * 256];     // dense matrix outputs [m][b][f] (post-GELU)

__device__ __forceinline__ float gelu_exact(float x) {
    return 0.5f * x * (1.0f + erff(x * 0.70710678118654752f));
}

// ---------------------------------------------------------------------------
// K0: transpose conv_w [64][286] -> g_cwT [(c*13+k)][64]; coalesced reads
// ---------------------------------------------------------------------------
__global__ void k0_transpose(const float* __restrict__ cw) {
    int d = blockIdx.x, ck = threadIdx.x;
    if (ck < 286) g_cwT[ck * 64 + d] = __ldg(cw + d * 286 + ck);
}

// ---------------------------------------------------------------------------
// K1: conv1d(stride2,pad6)+GELU+maxpool(3,3)+token LN (+cls LN in p==0 blocks)
// grid (6, 16) = (p, b), 192 threads = (qi 0..2) x (d 0..63)
// ---------------------------------------------------------------------------
__global__ void __launch_bounds__(192) k1_conv_pool_ln(
        const float* __restrict__ x,
        const float* __restrict__ cb,
        const float* __restrict__ cls,
        const float* __restrict__ tg,
        const float* __restrict__ tb) {
    __shared__ float xs[22][23];
    __shared__ float cv[3][64];
    int p = blockIdx.x, b = blockIdx.y, t = threadIdx.x;
    int base = 6 * p - 6;
    for (int l = t; l < 22 * 23; l += 192) {
        int c = l / 23, j = l - c * 23;
        int xi = base + j;
        xs[c][j] = (xi >= 0) ? x[(b * 22 + c) * 3000 + xi] : 0.f;
    }
    __syncthreads();
    {
        int qi = t / 64, d = t & 63;
        float acc = cb[d];
        #pragma unroll
        for (int c = 0; c < 22; c += 2) {
            float wv[26];
            #pragma unroll
            for (int k = 0; k < 26; k++)
                wv[k] = __ldg(g_cwT + (c * 13 + k) * 64 + d);
            #pragma unroll
            for (int k = 0; k < 13; k++) acc += wv[k] * xs[c][2 * qi + k];
            #pragma unroll
            for (int k = 0; k < 13; k++) acc += wv[13 + k] * xs[c + 1][2 * qi + k];
        }
        cv[qi][d] = gelu_exact(acc);
    }
    __syncthreads();
    if (t < 32) {
        float v0 = fmaxf(fmaxf(cv[0][t], cv[1][t]), cv[2][t]);
        float v1 = fmaxf(fmaxf(cv[0][t + 32], cv[1][t + 32]), cv[2][t + 32]);
        float s = v0 + v1;
        #pragma unroll
        for (int off = 16; off; off >>= 1) s += __shfl_xor_sync(0xffffffffu, s, off);
        float mean = s * (1.f / 64.f);
        float d0 = v0 - mean, d1 = v1 - mean;
        float q = d0 * d0 + d1 * d1;
        #pragma unroll
        for (int off = 16; off; off >>= 1) q += __shfl_xor_sync(0xffffffffu, q, off);
        float rstd = rsqrtf(q * (1.f / 64.f) + 1e-5f);
        float* dst = g_hln + b * 448 + (p + 1) * 64;
        dst[t]      = d0 * rstd * tg[t]      + tb[t];
        dst[t + 32] = d1 * rstd * tg[t + 32] + tb[t + 32];
    } else if (p == 0 && t < 64) {
        int lane = t - 32;
        float v0 = cls[lane], v1 = cls[lane + 32];
        float s = v0 + v1;
        #pragma unroll
        for (int off = 16; off; off >>= 1) s += __shfl_xor_sync(0xffffffffu, s, off);
        float mean = s * (1.f / 64.f);
        float d0 = v0 - mean, d1 = v1 - mean;
        float q = d0 * d0 + d1 * d1;
        #pragma unroll
        for (int off = 16; off; off >>= 1) q += __shfl_xor_sync(0xffffffffu, q, off);
        float rstd = rsqrtf(q * (1.f / 64.f) + 1e-5f);
        float* dst = g_hln + b * 448;
        dst[lane]      = d0 * rstd * tg[lane]      + tb[lane];
        dst[lane + 32] = d1 * rstd * tg[lane + 32] + tb[lane + 32];
    }
}

// ---------------------------------------------------------------------------
// K3 fused: fold ds_conv into ds_comp_w AND apply to tokens directly.
//   tokens_pre[b,o] = sum_{k<7,d} U[o,k,d]*hln[b,k,d] + sum_d U[o,7,d] + dcompb[o]
//   U[o,k,d] = sum_c W[o,c,d]*w1p[c,k]; w1p[c,7] = ds_conv_b[c]
// grid 256 (o), 1024 threads. W streamed as float4 via smem (dynamic 64KB).
// ---------------------------------------------------------------------------
__global__ void __launch_bounds__(1024) k3_fused(
        const float* __restrict__ W,
        const float* __restrict__ w1,
        const float* __restrict__ dcb,
        const float* __restrict__ dcompb) {
    extern __shared__ float ws[];     // 16384 floats = [c][d] tile for this o
    __shared__ float w1s[256 * 8];    // [c][k]; k=7 slot holds dcb[c]
    __shared__ float up[16][8][64];   // [cgrp][k][d] partials
    __shared__ float red[32][8];      // [warp][b-in-half]
    int o = blockIdx.x, t = threadIdx.x;
    int w = t >> 5, lane = t & 31;

    // taps
    for (int l = t; l < 2048; l += 1024) {
        int c = l >> 3, k = l & 7;
        w1s[l] = (k < 7) ? __ldg(w1 + c * 13 + 6 + k) : __ldg(dcb + c);
    }
    // W tile, coalesced float4, MLP=4
    {
        const float4* src = (const float4*)(W + (long)o * 16384);
        float4 v[4];
        #pragma unroll
        for (int i = 0; i < 4; i++) v[i] = __ldg(src + t + i * 1024);
        #pragma unroll
        for (int i = 0; i < 4; i++) ((float4*)ws)[t + i * 1024] = v[i];
    }
    __syncthreads();

    // phase A: cg covers 16 c's; fold taps
    {
        int cg = t >> 6, d = t & 63, c0 = cg * 16;
        float u[8] = {0.f, 0.f, 0.f, 0.f, 0.f, 0.f, 0.f, 0.f};
        #pragma unroll
        for (int j = 0; j < 16; j++) {
            float s = ws[(c0 + j) * 64 + d];
            const float4* wr = (const float4*)(w1s + (c0 + j) * 8);
            float4 wa = wr[0], wb = wr[1];
            u[0] += s * wa.x; u[1] += s * wa.y; u[2] += s * wa.z; u[3] += s * wa.w;
            u[4] += s * wb.x; u[5] += s * wb.y; u[6] += s * wb.z; u[7] += s * wb.w;
        }
        #pragma unroll
        for (int k = 0; k < 8; k++) up[cg][k][t & 63] = u[k];
    }
    __syncthreads();

    // phase B: group g2 = (bh, kk); dot with hln for 8 b's
    {
        int g2 = t >> 6, d = t & 63;
        int kk = g2 & 7, bh = g2 >> 3;
        float uf = 0.f;
        #pragma unroll
        for (int g = 0; g < 16; g++) uf += up[g][kk][d];

        float tpv[8];
        if (kk < 7) {
            float hv[8];
            const float* hp = g_hln + kk * 64 + d + bh * 8 * 448;
            #pragma unroll
            for (int i = 0; i < 8; i++) hv[i] = __ldg(hp + i * 448);
            #pragma unroll
            for (int i = 0; i < 8; i++) tpv[i] = uf * hv[i];
        } else {
            #pragma unroll
            for (int i = 0; i < 8; i++) tpv[i] = uf;
        }
        #pragma unroll
        for (int i = 0; i < 8; i++) {
            #pragma unroll
            for (int off = 16; off; off >>= 1)
                tpv[i] += __shfl_xor_sync(0xffffffffu, tpv[i], off);
        }
        if (lane < 8) red[w][lane] = tpv[lane];
    }
    __syncthreads();
    if (t < 16) {
        int b = t, base = (b >> 3) * 16;
        float s = 0.f;
        #pragma unroll
        for (int j = 0; j < 16; j++) s += red[base + j][b & 7];
        g_tp[b * 256 + o] = s + __ldg(dcompb + o);
    }
}

// ---------------------------------------------------------------------------
__device__ __forceinline__ float bsum256(float v, float* red) {
    #pragma unroll
    for (int off = 16; off; off >>= 1) v += __shfl_xor_sync(0xffffffffu, v, off);
    int w = threadIdx.x >> 5;
    if ((threadIdx.x & 31) == 0) red[w] = v;
    __syncthreads();
    if (threadIdx.x < 32) {
        float x = (threadIdx.x < 8) ? red[threadIdx.x] : 0.f;
        #pragma unroll
        for (int off = 4; off; off >>= 1) x += __shfl_xor_sync(0xffffffffu, x, off);
        if (threadIdx.x == 0) red[0] = x;
    }
    __syncthreads();
    float r = red[0];
    __syncthreads();
    return r;
}

// ---------------------------------------------------------------------------
// KA: LN(256)+GELU -> tokens (+transpose); gating -> g_coef. grid 16, 256 thr
// ---------------------------------------------------------------------------
__global__ void __launch_bounds__(256) kA_gate(
        const int* __restrict__ task_ids,
        const float* __restrict__ task_embed,
        const float* __restrict__ ds_g,
        const float* __restrict__ ds_b,
        const float* __restrict__ gate_w,
        const float* __restrict__ gate_b) {
    int b = blockIdx.x, t = threadIdx.x;
    int w = t >> 5, lane = t & 31;
    __shared__ float tok[256];
    __shared__ float red[32];
    __shared__ float gsh[8];

    // prefetch gating weights early (independent of the LN chain)
    int tid_task = __ldg(task_ids + b);
    float gw[8], gv[8], tev[8];
    {
        const float* te = task_embed + tid_task * 256;
        #pragma unroll
        for (int i = 0; i < 8; i++) {
            int o = lane + i * 32;
            gw[i]  = __ldg(gate_w + o * 8 + w);
            gv[i]  = __ldg(gate_w + (256 + o) * 8 + w);
            tev[i] = __ldg(te + o);
        }
    }

    float tp = g_tp[b * 256 + t];
    float mean = bsum256(tp, red) * (1.f / 256.f);
    float dv = tp - mean;
    float var = bsum256(dv * dv, red) * (1.f / 256.f);
    float rstd = rsqrtf(var + 1e-5f);
    float tv = gelu_exact(dv * rstd * __ldg(ds_g + t) + __ldg(ds_b + t));
    tok[t] = tv;
    g_tok[b * 256 + t] = tv;
    g_tokT[t * 16 + b] = tv;
    __syncthreads();

    // gating: warp e computes logit e
    {
        float s = 0.f;
        #pragma unroll
        for (int i = 0; i < 8; i++)
            s += tok[lane + i * 32] * gw[i] + tev[i] * gv[i];
        #pragma unroll
        for (int off = 16; off; off >>= 1) s += __shfl_xor_sync(0xffffffffu, s, off);
        if (lane == 0) gsh[w] = s + __ldg(gate_b + w);
    }
    __syncthreads();
    if (t == 0) {
        float v1 = -1e30f; int e1 = 0;
        #pragma unroll
        for (int e = 0; e < 8; e++) if (gsh[e] > v1) { v1 = gsh[e]; e1 = e; }
        float v2 = -1e30f; int e2 = 0;
        #pragma unroll
        for (int e = 0; e < 8; e++) if (e != e1 && gsh[e] > v2) { v2 = gsh[e]; e2 = e; }
        float g1 = 1.f / (1.f + expf(v2 - v1));
        float c[9];
        #pragma unroll
        for (int m = 0; m < 9; m++) c[m] = 0.f;
        c[e1] = g1;
        c[e2] = 1.f - g1;
        c[8]  = 1.f - g1;    // omega = 1 - max gate (g1 >= 0.5)
        #pragma unroll
        for (int m = 0; m < 9; m++) g_coef[b * 16 + m] = c[m];
    }
}

// ---------------------------------------------------------------------------
// KB3: dense matrices (8 experts + universal) for ALL b, weights read ONCE.
// grid (9, 16) = (matrix m, f-slice of 16 f). 256 threads.
// Each block: stage W[:, f0:f0+16] (16KB) + tokT (16KB) in smem, 4x4 reg tile.
// ---------------------------------------------------------------------------
__global__ void __launch_bounds__(256) kB3_dense(
        const float* __restrict__ exp_w,
        const float* __restrict__ exp_b,
        const float* __restrict__ uni_w,
        const float* __restrict__ uni_b) {
    __shared__ float wsm[4096];   // [d][16f] slice; reused as psm after compute
    __shared__ float tsm[4096];   // tokT [d][16b]
    int m = blockIdx.x, fs = blockIdx.y, t = threadIdx.x;
    int f0 = fs * 16;
    const float* Wb = (m < 8) ? exp_w + (long)m * 65536 : uni_w;

    // load W slice: thread: q = t&3 (f-quad), dbase = t>>2; 4 rows each
    {
        int q = t & 3, dbase = t >> 2;
        float4 v[4];
        #pragma unroll
        for (int i = 0; i < 4; i++) {
            int d = dbase + i * 64;
            v[i] = __ldg((const float4*)(Wb + d * 256 + f0) + q);
        }
        #pragma unroll
        for (int i = 0; i < 4; i++)
            ((float4*)wsm)[(dbase + i * 64) * 4 + q] = v[i];
    }
    // load tokT (contiguous)
    {
        float4 v[4];
        #pragma unroll
        for (int i = 0; i < 4; i++)
            v[i] = __ldg((const float4*)g_tokT + t + i * 256);
        #pragma unroll
        for (int i = 0; i < 4; i++)
            ((float4*)tsm)[t + i * 256] = v[i];
    }
    __syncthreads();

    // compute: thread = (dsl = t>>4 covering 16 d, bq = (t>>2)&3, fq = t&3)
    int dsl = t >> 4, bq = (t >> 2) & 3, fq = t & 3;
    float4 acc[4];
    #pragma unroll
    for (int i = 0; i < 4; i++) acc[i] = make_float4(0.f, 0.f, 0.f, 0.f);
    const float4* wsm4 = (const float4*)wsm;
    const float4* tsm4 = (const float4*)tsm;
    #pragma unroll
    for (int j = 0; j < 16; j++) {
        int d = dsl * 16 + j;
        float4 wq = wsm4[d * 4 + fq];   // 4 f's
        float4 tq = tsm4[d * 4 + bq];   // 4 b's
        acc[0].x += tq.x * wq.x; acc[0].y += tq.x * wq.y; acc[0].z += tq.x * wq.z; acc[0].w += tq.x * wq.w;
        acc[1].x += tq.y * wq.x; acc[1].y += tq.y * wq.y; acc[1].z += tq.y * wq.z; acc[1].w += tq.y * wq.w;
        acc[2].x += tq.z * wq.x; acc[2].y += tq.z * wq.y; acc[2].z += tq.z * wq.z; acc[2].w += tq.z * wq.w;
        acc[3].x += tq.w * wq.x; acc[3].y += tq.w * wq.y; acc[3].z += tq.w * wq.z; acc[3].w += tq.w * wq.w;
    }
    __syncthreads();   // all wsm reads done; reuse as psm
    float* psm = wsm;
    #pragma unroll
    for (int bi = 0; bi < 4; bi++) {
        int b = bq * 4 + bi;
        ((float4*)psm)[dsl * 64 + b * 4 + fq] = acc[bi];
    }
    __syncthreads();

    // final reduce over 16 dsl; one output per thread: (b = t>>4, fi = t&15)
    {
        int b = t >> 4, fi = t & 15;
        float s = 0.f;
        #pragma unroll
        for (int ds = 0; ds < 16; ds++) s += psm[ds * 256 + b * 16 + fi];
        float bias = (m < 8) ? __ldg(exp_b + m * 256 + f0 + fi) : __ldg(uni_b + f0 + fi);
        g_ye[(m * 16 + b) * 256 + f0 + fi] = gelu_exact(s + bias);
    }
}

// ---------------------------------------------------------------------------
// KC: weighted combine over 9 matrices + final LN. grid 16, 256 threads
// ---------------------------------------------------------------------------
__global__ void __launch_bounds__(256) kC_out(
        const float* __restrict__ out_g,
        const float* __restrict__ out_b,
        float* __restrict__ out) {
    int b = blockIdx.x, t = threadIdx.x;
    __shared__ float red[32];
    __shared__ float csm[9];
    if (t < 9) csm[t] = g_coef[b * 16 + t];
    __syncthreads();
    float ye[9];
    #pragma unroll
    for (int m = 0; m < 9; m++) ye[m] = __ldg(g_ye + (m * 16 + b) * 256 + t);
    float val = 0.f;
    #pragma unroll
    for (int m = 0; m < 9; m++) val += csm[m] * ye[m];
    float mn = bsum256(val, red) * (1.f / 256.f);
    float dv = val - mn;
    float v = bsum256(dv * dv, red) * (1.f / 256.f);
    float rs = rsqrtf(v + 1e-5f);
    out[b * 256 + t] = dv * rs * __ldg(out_g + t) + __ldg(out_b + t);
}

// ---------------------------------------------------------------------------
extern "C" void kernel_launch(void* const* d_in, const int* in_sizes, int n_in,
                              void* d_out, int out_size) {
    const float* x_stream   = (const float*)d_in[0];
    const int*   task_ids   = (const int*)  d_in[1];
    const float* conv_w     = (const float*)d_in[2];
    const float* conv_b     = (const float*)d_in[3];
    const float* cls_token  = (const float*)d_in[4];
    const float* tok_g      = (const float*)d_in[5];
    const float* tok_b      = (const float*)d_in[6];
    const float* ds_conv_w  = (const float*)d_in[7];
    const float* ds_conv_b  = (const float*)d_in[8];
    const float* ds_comp_w  = (const float*)d_in[9];
    const float* ds_comp_b  = (const float*)d_in[10];
    const float* ds_g       = (const float*)d_in[11];
    const float* ds_b       = (const float*)d_in[12];
    const float* task_embed = (const float*)d_in[13];
    const float* gate_w     = (const float*)d_in[14];
    const float* gate_b     = (const float*)d_in[15];
    const float* exp_w      = (const float*)d_in[16];
    const float* exp_b      = (const float*)d_in[17];
    const float* uni_w      = (const float*)d_in[18];
    const float* uni_b      = (const float*)d_in[19];
    const float* out_g      = (const float*)d_in[20];
    const float* out_b      = (const float*)d_in[21];
    float* out = (float*)d_out;

    static_assert(sizeof(float4) == 16, "");
    cudaFuncSetAttribute(k3_fused, cudaFuncAttributeMaxDynamicSharedMemorySize,
                         16384 * sizeof(float));

    k0_transpose<<<64, 286>>>(conv_w);
    k1_conv_pool_ln<<<dim3(6, 16), 192>>>(x_stream, conv_b, cls_token, tok_g, tok_b);
    k3_fused<<<256, 1024, 16384 * sizeof(float)>>>(ds_comp_w, ds_conv_w, ds_conv_b, ds_comp_b);
    kA_gate<<<16, 256>>>(task_ids, task_embed, ds_g, ds_b, gate_w, gate_b);
    kB3_dense<<<dim3(9, 16), 256>>>(exp_w, exp_b, uni_w, uni_b);
    kC_out<<<16, 256>>>(out_g, out_b, out);
}